// round 17
// baseline (speedup 1.0000x reference)
#include <cuda_runtime.h>

// Thole dipole-dipole interaction tensor.
//   t[e] = 3*lambda5*inv_r5 * v v^T  -  lambda3*inv_r3 * I3
// Inputs (metadata order): species(i32,N) [unused], edge_src(i32,E),
// edge_dst(i32,E), distances(f32,E), vec(f32,3E), polarisability(f32,N).
// Output: f32, E*9.
//
// R16 WIN (88.8us): warp-autonomous, no CTA barriers, warp-private slab
// transpose. ncu: L1 74.4%, DRAM 48.3%, issue 19.3% -> latency still partly
// exposed; wavefront wall ~64-68us. This round: ITEMS 2->4 per lane to double
// per-thread gather MLP (8 chains in flight). smem 36KB, occ ~65% expected;
// net in-flight ~x1.4.

#define BOHR_F 0.52917721067f
#define A_MUTUAL_F 0.39f

static constexpr int TPB   = 256;
static constexpr int WARPS = TPB / 32;
static constexpr int ITEMS = 4;                  // edges per lane
static constexpr int EPW   = 32 * ITEMS;         // 128 edges per warp
static constexpr int EPB   = TPB * ITEMS;        // 1024 edges per block

__global__ __launch_bounds__(TPB)
void polarisation_kernel(const int* __restrict__ edge_src,
                         const int* __restrict__ edge_dst,
                         const float* __restrict__ distances,
                         const float* __restrict__ vec,
                         const float* __restrict__ pol,
                         float* __restrict__ out,
                         int E) {
    // Warp-private slabs: EPW*9 = 1152 floats = 288 float4 per warp. 36 KB/CTA.
    __shared__ float s_slab[WARPS][EPW * 9];

    const int lane = threadIdx.x & 31;
    const int wid  = threadIdx.x >> 5;
    const int block_start = blockIdx.x * EPB;
    const int wbase = block_start + wid * EPW;    // this warp's first edge

    const float inv_bohr = 1.0f / BOHR_F;
    const float inv_b6 = inv_bohr * inv_bohr * inv_bohr *
                         inv_bohr * inv_bohr * inv_bohr;

    float* slab = s_slab[wid];

    if (wbase + EPW <= E) {
        // ---------------- fast path (no CTA sync anywhere) ----------------
        int   si[ITEMS], di[ITEMS];
        float ps[ITEMS], pd[ITEMS];
        float rr[ITEMS];
        float vv[ITEMS][3];

        // gather chain first (longest latency): idx then pol
        #pragma unroll
        for (int j = 0; j < ITEMS; j++) {
            const int e = wbase + j * 32 + lane;
            si[j] = __ldcs(&edge_src[e]);
            di[j] = __ldcs(&edge_dst[e]);
        }
        #pragma unroll
        for (int j = 0; j < ITEMS; j++) {
            ps[j] = __ldg(&pol[si[j]]);
            pd[j] = __ldg(&pol[di[j]]);
        }

        // independent streaming loads overlap the gather latency
        #pragma unroll
        for (int j = 0; j < ITEMS; j++) {
            const int e = wbase + j * 32 + lane;
            rr[j] = __ldcs(&distances[e]);
            vv[j][0] = __ldcs(&vec[e * 3 + 0]);
            vv[j][1] = __ldcs(&vec[e * 3 + 1]);
            vv[j][2] = __ldcs(&vec[e * 3 + 2]);
        }

        #pragma unroll
        for (int j = 0; j < ITEMS; j++) {
            const float r  = rr[j] * inv_bohr;
            const float vx = vv[j][0] * inv_bohr;
            const float vy = vv[j][1] * inv_bohr;
            const float vz = vv[j][2] * inv_bohr;
            const float alpha_ij = ps[j] * pd[j] * inv_b6;

            const float inv_r  = __fdividef(1.0f, r);
            const float inv_r2 = inv_r * inv_r;
            const float inv_r3 = inv_r2 * inv_r;
            const float inv_r5 = inv_r3 * inv_r2;

            // a*u^3 = a * r^3 / sqrt(alpha_ij)
            const float au3 = A_MUTUAL_F * (r * r * r) * rsqrtf(alpha_ij);
            const float ex  = __expf(-au3);
            const float lambda3 = 1.0f - ex;
            const float lambda5 = 1.0f - (1.0f + au3) * ex;

            const float c5 = 3.0f * lambda5 * inv_r5;
            const float c3 = lambda3 * inv_r3;

            // stride-9 smem writes within the warp slab: gcd(9,32)=1 -> clean
            float* o = &slab[(j * 32 + lane) * 9];
            o[0] = c5 * vx * vx - c3;
            o[1] = c5 * vx * vy;
            o[2] = c5 * vx * vz;
            o[3] = c5 * vy * vx;
            o[4] = c5 * vy * vy - c3;
            o[5] = c5 * vy * vz;
            o[6] = c5 * vz * vx;
            o[7] = c5 * vz * vy;
            o[8] = c5 * vz * vz - c3;
        }

        __syncwarp();

        // warp-cooperative coalesced store: 288 contiguous float4
        {
            const float4* slab4 = (const float4*)slab;
            float4* out4 = (float4*)out;
            const long long gbase4 = (long long)wbase * 9 / 4;  // wbase%32==0
            #pragma unroll
            for (int k = 0; k < EPW * 9 / 4 / 32; k++) {        // 9 iters
                const int idx = lane + k * 32;
                __stcs(&out4[gbase4 + idx], slab4[idx]);
            }
        }
    } else {
        // ---------------- tail path: direct scalar stores ----------------
        #pragma unroll
        for (int j = 0; j < ITEMS; j++) {
            const int e = wbase + j * 32 + lane;
            if (e < E) {
                const float r  = distances[e] * inv_bohr;
                const float vx = vec[e * 3 + 0] * inv_bohr;
                const float vy = vec[e * 3 + 1] * inv_bohr;
                const float vz = vec[e * 3 + 2] * inv_bohr;
                const float alpha_ij = __ldg(&pol[edge_src[e]]) *
                                       __ldg(&pol[edge_dst[e]]) * inv_b6;

                const float inv_r  = __fdividef(1.0f, r);
                const float inv_r2 = inv_r * inv_r;
                const float inv_r3 = inv_r2 * inv_r;
                const float inv_r5 = inv_r3 * inv_r2;

                const float au3 = A_MUTUAL_F * (r * r * r) * rsqrtf(alpha_ij);
                const float ex  = __expf(-au3);
                const float lambda3 = 1.0f - ex;
                const float lambda5 = 1.0f - (1.0f + au3) * ex;

                const float c5 = 3.0f * lambda5 * inv_r5;
                const float c3 = lambda3 * inv_r3;

                float* o = &out[(long long)e * 9];
                o[0] = c5 * vx * vx - c3;
                o[1] = c5 * vx * vy;
                o[2] = c5 * vx * vz;
                o[3] = c5 * vy * vx;
                o[4] = c5 * vy * vy - c3;
                o[5] = c5 * vy * vz;
                o[6] = c5 * vz * vx;
                o[7] = c5 * vz * vy;
                o[8] = c5 * vz * vz - c3;
            }
        }
    }
}

extern "C" void kernel_launch(void* const* d_in, const int* in_sizes, int n_in,
                              void* d_out, int out_size) {
    // metadata order: species, edge_src, edge_dst, distances, vec, polarisability
    const int*   edge_src = (const int*)d_in[1];
    const int*   edge_dst = (const int*)d_in[2];
    const float* dist     = (const float*)d_in[3];
    const float* vec      = (const float*)d_in[4];
    const float* pol      = (const float*)d_in[5];
    float* out = (float*)d_out;

    const int E = in_sizes[1];
    const int blocks = (E + EPB - 1) / EPB;
    polarisation_kernel<<<blocks, TPB>>>(edge_src, edge_dst, dist, vec, pol, out, E);
}